// round 13
// baseline (speedup 1.0000x reference)
#include <cuda_runtime.h>
#include <cuda_fp16.h>
#include <mma.h>
#include <math.h>
#include <stdint.h>
#include <cstdint>

using namespace nvcuda;

#define AS 136    // fp16 tile stride (halfs, mult of 8)
#define FS 136    // f32 scratch stride (floats)
#define HS2 136   // half scratch stride (halfs)
#define SHS 72    // fp16 score row stride (halfs, mult of 8)
#define HB (64*SHS)  // per-head S block (halfs)
#define WS64 72   // 64-col weight chunk stride (halfs)
#define WBUF 18432  // bytes per 64-col chunk buffer (128*72*2)

// fp16 pre-converted weights (written by cvt_weights_kernel each launch)
// Q columns of qkv_w are pre-scaled by 1/sqrt(HD).
__device__ __align__(16) __half g_qkvwh[128*384];
__device__ __align__(16) __half g_projwh[128*128];
__device__ __align__(16) __half g_w1h[128*512];
__device__ __align__(16) __half g_w2h[512*128];

// ---------------------------------------------------------------------------
__global__ void cvt_weights_kernel(const float* __restrict__ qkv_w,
                                   const float* __restrict__ proj_w,
                                   const float* __restrict__ w1,
                                   const float* __restrict__ w2)
{
    const int i4 = (blockIdx.x*256 + threadIdx.x) * 4;   // grid 192 -> 196608
    const float* src; __half* dst; int off;
    float scale = 1.f;
    if (i4 < 49152) {
        src = qkv_w;  dst = g_qkvwh;  off = i4;
        if ((off % 384) < 128) scale = 0.17677669529663687f;   // fold qscale into Q
    }
    else if (i4 < 65536)  { src = proj_w; dst = g_projwh; off = i4 - 49152; }
    else if (i4 < 131072) { src = w1;     dst = g_w1h;    off = i4 - 65536; }
    else                  { src = w2;     dst = g_w2h;    off = i4 - 131072; }
    const float4 v = *(const float4*)(src + off);
    dst[off+0] = __float2half(v.x*scale); dst[off+1] = __float2half(v.y*scale);
    dst[off+2] = __float2half(v.z*scale); dst[off+3] = __float2half(v.w*scale);
}

// ---------------------------------------------------------------------------
__device__ __forceinline__ uint32_t smem_u32(const void* p) {
    uint32_t a;
    asm("{ .reg .u64 t; cvta.to.shared.u64 t, %1; cvt.u32.u64 %0, t; }"
        : "=r"(a) : "l"(p));
    return a;
}
__device__ __forceinline__ void cp16(uint32_t dst, const void* src) {
    asm volatile("cp.async.cg.shared.global [%0], [%1], 16;" :: "r"(dst), "l"(src));
}
#define CP_COMMIT() asm volatile("cp.async.commit_group;" ::: "memory")
#define CP_WAIT(N)  asm volatile("cp.async.wait_group %0;" :: "n"(N) : "memory")

// ---------------------------------------------------------------------------
// Kernel A v6: cp.async double-buffered QKV/proj weight pipeline.
// LN1 -> QKV(6x64-col pipelined chunks, half acc) -> all-heads attention ->
// proj(2x64-col, output into Qh) -> residual scatter. 2 CTA/SM.
// ---------------------------------------------------------------------------
__global__ void __launch_bounds__(256, 2) swin_attn_kernel(
    const float* __restrict__ inp,
    const float* __restrict__ proj_b,
    const float* __restrict__ bias_table,
    const float* __restrict__ g1,
    const float* __restrict__ b1,
    float* __restrict__ out)
{
    extern __shared__ char sma[];
    __half* Xh = (__half*)sma;            // 64*AS (LN'd X; later O fp16)
    __half* Qh = Xh + 64*AS;              // Q; later proj output
    __half* Kh = Qh + 64*AS;
    __half* Vh = Kh + 64*AS;
    char*   U  = (char*)(Vh + 64*AS);     // 36864B: 2 weight bufs / Sh
    __half* Sh = (__half*)U;              // 4*HB halfs (36864B)
    float*  bias_s = (float*)(U + 36864); // 484
    int*    lab_s  = (int*)(bias_s + 484);
    int*    orow_s = lab_s + 64;

    const uint32_t Ubase = smem_u32(U);

    const int tid = threadIdx.x;
    const int warp = tid >> 5, lane = tid & 31;
    const int wblk = blockIdx.x;
    const int bb = wblk >> 9;
    const int wi = wblk & 511;
    const int gx = wi >> 6, gy = (wi >> 3) & 7, gz = wi & 7;

    // issue QKV chunks 0 and 1 (cp.async) before anything else
    #pragma unroll
    for (int c0 = 0; c0 < 2; ++c0) {
        const int cbase = (c0 >> 1)*128 + (c0 & 1)*64;
        const uint32_t wb = Ubase + c0*WBUF;
        for (int i = tid; i < 1024; i += 256) {
            const int row = i >> 3, seg = i & 7;
            cp16(wb + (uint32_t)(row*WS64 + seg*8)*2,
                 g_qkvwh + row*384 + cbase + seg*8);
        }
        CP_COMMIT();
    }

    for (int i = tid; i < 484; i += 256) bias_s[i] = bias_table[i];

    if (tid < 64) {
        const int lx = tid >> 4, ly = (tid >> 2) & 3, lz = tid & 3;
        const int px = gx*4 + lx, py = gy*4 + ly, pz = gz*4 + lz;
        const int ox = (px + 2) & 31, oy = (py + 2) & 31, oz = (pz + 2) & 31;
        orow_s[tid] = ((bb*32 + ox)*32 + oy)*32 + oz;
        const int labx = px < 28 ? 0 : (px < 30 ? 1 : 2);
        const int laby = py < 28 ? 0 : (py < 30 ? 1 : 2);
        const int labz = pz < 28 ? 0 : (pz < 30 ? 1 : 2);
        lab_s[tid] = labx*9 + laby*3 + labz;
    }
    __syncthreads();

    // ---- Phase 1: LayerNorm -> fp16 Xh (overlaps chunk 0/1 arrival) ----
    {
        const float4 gv = *(const float4*)(g1 + lane*4);
        const float4 bv = *(const float4*)(b1 + lane*4);
        for (int t = warp*8; t < warp*8 + 8; ++t) {
            const float* row = inp + (long)orow_s[t]*128;
            const float4 x4 = *(const float4*)(row + lane*4);
            float s = x4.x + x4.y + x4.z + x4.w;
            float q = x4.x*x4.x + x4.y*x4.y + x4.z*x4.z + x4.w*x4.w;
            #pragma unroll
            for (int o = 16; o; o >>= 1) {
                s += __shfl_xor_sync(0xffffffffu, s, o);
                q += __shfl_xor_sync(0xffffffffu, q, o);
            }
            const float m = s * 0.0078125f;
            const float rstd = rsqrtf(q*0.0078125f - m*m + 1e-5f);
            __half* dst = Xh + t*AS + lane*4;
            dst[0] = __float2half((x4.x - m)*rstd*gv.x + bv.x);
            dst[1] = __float2half((x4.y - m)*rstd*gv.y + bv.y);
            dst[2] = __float2half((x4.z - m)*rstd*gv.z + bv.z);
            dst[3] = __float2half((x4.w - m)*rstd*gv.w + bv.w);
        }
    }

    const int rw = warp >> 2;             // 32-row half (0..1)
    const int cw = warp & 3;              // 16-col slot (0..3)

    // ---- Phase 2: QKV, 6 pipelined 64-col chunks, half acc ----
    #pragma unroll 1
    for (int c = 0; c < 6; ++c) {
        if (c < 5) { CP_WAIT(1); } else { CP_WAIT(0); }
        __syncthreads();                  // chunk c visible (+ Xh on c==0)
        {
            __half* Wb = (__half*)(U + (c & 1)*WBUF);
            wmma::fragment<wmma::accumulator, 16, 16, 16, __half> c1[2];
            #pragma unroll
            for (int i = 0; i < 2; ++i) wmma::fill_fragment(c1[i], __float2half(0.f));
            #pragma unroll
            for (int ks = 0; ks < 8; ++ks) {
                wmma::fragment<wmma::matrix_a, 16, 16, 16, __half, wmma::row_major> fa[2];
                wmma::fragment<wmma::matrix_b, 16, 16, 16, __half, wmma::row_major> fb;
                #pragma unroll
                for (int i = 0; i < 2; ++i)
                    wmma::load_matrix_sync(fa[i], Xh + (rw*32 + i*16)*AS + ks*16, AS);
                wmma::load_matrix_sync(fb, Wb + ks*16*WS64 + cw*16, WS64);
                #pragma unroll
                for (int i = 0; i < 2; ++i) wmma::mma_sync(c1[i], fa[i], fb, c1[i]);
            }
            __half* dest = (c < 2) ? Qh : (c < 4) ? Kh : Vh;
            const int colb = (c & 1)*64 + cw*16;
            #pragma unroll
            for (int i = 0; i < 2; ++i)
                wmma::store_matrix_sync(dest + (rw*32 + i*16)*AS + colb, c1[i], AS, wmma::mem_row_major);
        }
        __syncthreads();                  // buf[c&1] reads done
        if (c < 4) {                      // issue chunk c+2 into buf[c&1]
            const int cn = c + 2;
            const int cbase = (cn >> 1)*128 + (cn & 1)*64;
            const uint32_t wb = Ubase + (c & 1)*WBUF;
            for (int i = tid; i < 1024; i += 256) {
                const int row = i >> 3, seg = i & 7;
                cp16(wb + (uint32_t)(row*WS64 + seg*8)*2,
                     g_qkvwh + row*384 + cbase + seg*8);
            }
            CP_COMMIT();
        }
    }
    // Q/K/V ready; U free -> Sh

    // ---- Phase 3: all-heads attention ----
    {
        const int h = warp >> 1;
        const int p = warp & 1;
        wmma::fragment<wmma::accumulator, 16, 16, 16, __half> sc[2][4];
        #pragma unroll
        for (int i = 0; i < 2; ++i)
            #pragma unroll
            for (int j = 0; j < 4; ++j) wmma::fill_fragment(sc[i][j], __float2half(0.f));
        #pragma unroll
        for (int ks = 0; ks < 2; ++ks) {
            wmma::fragment<wmma::matrix_a, 16, 16, 16, __half, wmma::row_major> fa[2];
            wmma::fragment<wmma::matrix_b, 16, 16, 16, __half, wmma::col_major> fb[4];
            #pragma unroll
            for (int i = 0; i < 2; ++i)
                wmma::load_matrix_sync(fa[i], Qh + (p*32 + i*16)*AS + h*32 + ks*16, AS);
            #pragma unroll
            for (int j = 0; j < 4; ++j)
                wmma::load_matrix_sync(fb[j], Kh + j*16*AS + h*32 + ks*16, AS);
            #pragma unroll
            for (int i = 0; i < 2; ++i)
                #pragma unroll
                for (int j = 0; j < 4; ++j) wmma::mma_sync(sc[i][j], fa[i], fb[j], sc[i][j]);
        }
        #pragma unroll
        for (int i = 0; i < 2; ++i)
            #pragma unroll
            for (int j = 0; j < 4; ++j)
                wmma::store_matrix_sync(Sh + h*HB + (p*32 + i*16)*SHS + j*16, sc[i][j], SHS, wmma::mem_row_major);
    }
    __syncthreads();

    // softmax: one thread per (head, row), fully in registers (half2)
    {
        const int shh = tid >> 6;
        const int si  = tid & 63;
        __half* Srow = Sh + shh*HB + si*SHS;
        const int li = lab_s[si];
        const int lxi = si >> 4, lyi = (si >> 2) & 3, lzi = si & 3;
        half2 av[32];
        float mx = -1e30f;
        #pragma unroll
        for (int t = 0; t < 32; ++t) {
            const int j0 = 2*t;
            const float2 s2 = __half22float2(*(half2*)(Srow + j0));
            const int lxj = j0 >> 4, lyj = (j0 >> 2) & 3, lzj = j0 & 3;
            const int brow = 11*(lxi - lxj + 3) + (lyi - lyj + 3) + (lzi - lzj + 3);
            float a0 = s2.x + bias_s[brow*4 + shh];
            float a1 = s2.y + bias_s[(brow-1)*4 + shh];
            if (lab_s[j0]   != li) a0 -= 100.f;
            if (lab_s[j0+1] != li) a1 -= 100.f;
            mx = fmaxf(mx, fmaxf(a0, a1));
            av[t] = __floats2half2_rn(a0, a1);
        }
        const half2 mx2 = __float2half2_rn(mx);
        float sum = 0.f;
        #pragma unroll
        for (int t = 0; t < 32; ++t) {
            av[t] = h2exp(__hsub2(av[t], mx2));
            const float2 e2 = __half22float2(av[t]);
            sum += e2.x + e2.y;
        }
        const half2 inv2 = __float2half2_rn(1.f / sum);
        #pragma unroll
        for (int t = 0; t < 32; ++t)
            *(half2*)(Srow + 2*t) = __hmul2(av[t], inv2);
    }
    __syncthreads();

    // PV (all heads): half acc, store direct into Xh
    {
        const int hh = warp & 3;
        const int rp = warp >> 2;
        wmma::fragment<wmma::accumulator, 16, 16, 16, __half> oc[2][2];
        #pragma unroll
        for (int i = 0; i < 2; ++i)
            #pragma unroll
            for (int j = 0; j < 2; ++j) wmma::fill_fragment(oc[i][j], __float2half(0.f));
        #pragma unroll
        for (int ks = 0; ks < 4; ++ks) {
            wmma::fragment<wmma::matrix_a, 16, 16, 16, __half, wmma::row_major> fa[2];
            wmma::fragment<wmma::matrix_b, 16, 16, 16, __half, wmma::row_major> fb[2];
            #pragma unroll
            for (int i = 0; i < 2; ++i)
                wmma::load_matrix_sync(fa[i], Sh + hh*HB + (rp*32 + i*16)*SHS + ks*16, SHS);
            #pragma unroll
            for (int j = 0; j < 2; ++j)
                wmma::load_matrix_sync(fb[j], Vh + ks*16*AS + hh*32 + j*16, AS);
            #pragma unroll
            for (int i = 0; i < 2; ++i)
                #pragma unroll
                for (int j = 0; j < 2; ++j) wmma::mma_sync(oc[i][j], fa[i], fb[j], oc[i][j]);
        }
        #pragma unroll
        for (int i = 0; i < 2; ++i)
            #pragma unroll
            for (int j = 0; j < 2; ++j)
                wmma::store_matrix_sync(Xh + (rp*32 + i*16)*AS + hh*32 + j*16, oc[i][j], AS, wmma::mem_row_major);
    }
    __syncthreads();      // Sh reads done -> U free; Xh (O) visible

    // ---- Phase 4: proj (2x64-col chunks, both prefetched), out -> Qh ----
    #pragma unroll
    for (int pc = 0; pc < 2; ++pc) {
        const uint32_t wb = Ubase + pc*WBUF;
        for (int i = tid; i < 1024; i += 256) {
            const int row = i >> 3, seg = i & 7;
            cp16(wb + (uint32_t)(row*WS64 + seg*8)*2,
                 g_projwh + row*128 + pc*64 + seg*8);
        }
        CP_COMMIT();
    }
    CP_WAIT(0);
    __syncthreads();
    #pragma unroll
    for (int pc = 0; pc < 2; ++pc) {
        __half* Wb = (__half*)(U + pc*WBUF);
        wmma::fragment<wmma::accumulator, 16, 16, 16, __half> c1[2];
        #pragma unroll
        for (int i = 0; i < 2; ++i) wmma::fill_fragment(c1[i], __float2half(0.f));
        #pragma unroll
        for (int ks = 0; ks < 8; ++ks) {
            wmma::fragment<wmma::matrix_a, 16, 16, 16, __half, wmma::row_major> fa[2];
            wmma::fragment<wmma::matrix_b, 16, 16, 16, __half, wmma::row_major> fb;
            #pragma unroll
            for (int i = 0; i < 2; ++i)
                wmma::load_matrix_sync(fa[i], Xh + (rw*32 + i*16)*AS + ks*16, AS);
            wmma::load_matrix_sync(fb, Wb + ks*16*WS64 + cw*16, WS64);
            #pragma unroll
            for (int i = 0; i < 2; ++i) wmma::mma_sync(c1[i], fa[i], fb, c1[i]);
        }
        #pragma unroll
        for (int i = 0; i < 2; ++i)
            wmma::store_matrix_sync(Qh + (rw*32 + i*16)*AS + pc*64 + cw*16, c1[i], AS, wmma::mem_row_major);
    }
    __syncthreads();

    for (int idx = tid; idx < 2048; idx += 256) {
        const int r = idx >> 5, cg = idx & 31;
        const long base = (long)orow_s[r]*128;
        const half2 v01 = *(half2*)(Qh + r*AS + cg*4);
        const half2 v23 = *(half2*)(Qh + r*AS + cg*4 + 2);
        const float2 f01 = __half22float2(v01);
        const float2 f23 = __half22float2(v23);
        const float4 pb = *(const float4*)(proj_b + cg*4);
        const float4 xin = *(const float4*)(inp + base + cg*4);
        float4 o;
        o.x = 0.5f*(f01.x + pb.x) + xin.x;
        o.y = 0.5f*(f01.y + pb.y) + xin.y;
        o.z = 0.5f*(f23.x + pb.z) + xin.z;
        o.w = 0.5f*(f23.y + pb.w) + xin.w;
        *(float4*)(out + base + cg*4) = o;
    }
}

// ---------------------------------------------------------------------------
// Kernel B (UNCHANGED from passing round 12): wmma fp16 MLP, 3 CTA/SM.
// ---------------------------------------------------------------------------
__global__ void __launch_bounds__(256, 3) swin_mlp_kernel(
    const float* __restrict__ bb1, const float* __restrict__ bb2,
    const float* __restrict__ g2, const float* __restrict__ b2,
    float* __restrict__ io)
{
    extern __shared__ char smraw[];
    __half* A1 = (__half*)smraw;          // 64*AS
    __half* A2 = A1 + 64*AS;              // 64*AS
    char*   U  = (char*)(A2 + 64*AS);     // 34816B union
    __half* Wc = (__half*)U;              // weights
    __half* Hs = (__half*)U;              // half scratch (64*HS2)
    float*  Ff = (float*)U;               // f32 scratch (final epilogue)

    const int tid  = threadIdx.x;
    const int warp = tid >> 5, lane = tid & 31;
    const long row0 = (long)blockIdx.x * 64;

    {
        const float4 gv = *(const float4*)(g2 + lane*4);
        const float4 bv = *(const float4*)(b2 + lane*4);
        for (int t = warp*8; t < warp*8 + 8; ++t) {
            const float* row = io + (row0 + t)*128;
            const float4 x4 = *(const float4*)(row + lane*4);
            float s = x4.x + x4.y + x4.z + x4.w;
            float q = x4.x*x4.x + x4.y*x4.y + x4.z*x4.z + x4.w*x4.w;
            #pragma unroll
            for (int o = 16; o; o >>= 1) {
                s += __shfl_xor_sync(0xffffffffu, s, o);
                q += __shfl_xor_sync(0xffffffffu, q, o);
            }
            const float m = s * 0.0078125f;
            const float rstd = rsqrtf(q*0.0078125f - m*m + 1e-5f);
            __half* dst = A1 + t*AS + lane*4;
            dst[0] = __float2half((x4.x - m)*rstd*gv.x + bv.x);
            dst[1] = __float2half((x4.y - m)*rstd*gv.y + bv.y);
            dst[2] = __float2half((x4.z - m)*rstd*gv.z + bv.z);
            dst[3] = __float2half((x4.w - m)*rstd*gv.w + bv.w);
        }
    }

    const int rt2 = warp >> 2;   // 32-row half
    const int ct2 = warp & 3;    // 32-col quarter

    wmma::fragment<wmma::accumulator, 16, 16, 16, float> acc2[2][2];
    #pragma unroll
    for (int i = 0; i < 2; ++i)
        #pragma unroll
        for (int j = 0; j < 2; ++j) wmma::fill_fragment(acc2[i][j], 0.f);

    for (int nb = 0; nb < 4; ++nb) {
        __syncthreads();
        for (int idx = tid; idx < 2048; idx += 256) {
            const int k = idx >> 4, u = idx & 15;
            *(uint4*)(Wc + k*AS + u*8) = *(const uint4*)(g_w1h + k*512 + nb*128 + u*8);
        }
        __syncthreads();

        wmma::fragment<wmma::accumulator, 16, 16, 16, __half> c1[2][2];
        #pragma unroll
        for (int i = 0; i < 2; ++i)
            #pragma unroll
            for (int j = 0; j < 2; ++j) wmma::fill_fragment(c1[i][j], __float2half(0.f));
        #pragma unroll
        for (int ks = 0; ks < 8; ++ks) {
            wmma::fragment<wmma::matrix_a, 16, 16, 16, __half, wmma::row_major> fa[2];
            wmma::fragment<wmma::matrix_b, 16, 16, 16, __half, wmma::row_major> fb[2];
            #pragma unroll
            for (int i = 0; i < 2; ++i)
                wmma::load_matrix_sync(fa[i], A1 + (rt2*32 + i*16)*AS + ks*16, AS);
            #pragma unroll
            for (int j = 0; j < 2; ++j)
                wmma::load_matrix_sync(fb[j], Wc + ks*16*AS + ct2*32 + j*16, AS);
            #pragma unroll
            for (int i = 0; i < 2; ++i)
                #pragma unroll
                for (int j = 0; j < 2; ++j) wmma::mma_sync(c1[i][j], fa[i], fb[j], c1[i][j]);
        }
        __syncthreads();
        #pragma unroll
        for (int i = 0; i < 2; ++i)
            #pragma unroll
            for (int j = 0; j < 2; ++j)
                wmma::store_matrix_sync(Hs + (rt2*32 + i*16)*HS2 + ct2*32 + j*16, c1[i][j], HS2, wmma::mem_row_major);
        __syncthreads();

        for (int idx = tid; idx < 2048; idx += 256) {
            const int r = idx >> 5, cg = idx & 31;
            const half2 v01 = *(half2*)(Hs + r*HS2 + cg*4);
            const half2 v23 = *(half2*)(Hs + r*HS2 + cg*4 + 2);
            const float2 f01 = __half22float2(v01);
            const float2 f23 = __half22float2(v23);
            const float4 bv = *(const float4*)(bb1 + nb*128 + cg*4);
            float h0 = f01.x + bv.x, h1 = f01.y + bv.y, h2 = f23.x + bv.z, h3 = f23.y + bv.w;
            h0 = h0 * 0.5f * (1.f + erff(h0 * 0.70710678118654752f));
            h1 = h1 * 0.5f * (1.f + erff(h1 * 0.70710678118654752f));
            h2 = h2 * 0.5f * (1.f + erff(h2 * 0.70710678118654752f));
            h3 = h3 * 0.5f * (1.f + erff(h3 * 0.70710678118654752f));
            __half* dst = A2 + r*AS + cg*4;
            dst[0] = __float2half(h0); dst[1] = __float2half(h1);
            dst[2] = __float2half(h2); dst[3] = __float2half(h3);
        }
        __syncthreads();
        for (int idx = tid; idx < 2048; idx += 256) {
            const int k = idx >> 4, u = idx & 15;
            *(uint4*)(Wc + k*AS + u*8) = *(const uint4*)(g_w2h + (nb*128 + k)*128 + u*8);
        }
        __syncthreads();

        #pragma unroll
        for (int ks = 0; ks < 8; ++ks) {
            wmma::fragment<wmma::matrix_a, 16, 16, 16, __half, wmma::row_major> fa[2];
            wmma::fragment<wmma::matrix_b, 16, 16, 16, __half, wmma::row_major> fb[2];
            #pragma unroll
            for (int i = 0; i < 2; ++i)
                wmma::load_matrix_sync(fa[i], A2 + (rt2*32 + i*16)*AS + ks*16, AS);
            #pragma unroll
            for (int j = 0; j < 2; ++j)
                wmma::load_matrix_sync(fb[j], Wc + ks*16*AS + ct2*32 + j*16, AS);
            #pragma unroll
            for (int i = 0; i < 2; ++i)
                #pragma unroll
                for (int j = 0; j < 2; ++j) wmma::mma_sync(acc2[i][j], fa[i], fb[j], acc2[i][j]);
        }
    }

    __syncthreads();
    #pragma unroll
    for (int i = 0; i < 2; ++i)
        #pragma unroll
        for (int j = 0; j < 2; ++j)
            wmma::store_matrix_sync(Ff + (rt2*32 + i*16)*FS + ct2*32 + j*16, acc2[i][j], FS, wmma::mem_row_major);
    __syncthreads();

    for (int idx = tid; idx < 2048; idx += 256) {
        const int r = idx >> 5, cg = idx & 31;
        const float4 v  = *(const float4*)(Ff + r*FS + cg*4);
        const float4 bv = *(const float4*)(bb2 + cg*4);
        float* gp = io + (row0 + r)*128 + cg*4;
        const float4 xv = *(const float4*)gp;
        float4 o;
        o.x = 0.5f*(v.x + bv.x) + xv.x;
        o.y = 0.5f*(v.y + bv.y) + xv.y;
        o.z = 0.5f*(v.z + bv.z) + xv.z;
        o.w = 0.5f*(v.w + bv.w) + xv.w;
        *(float4*)gp = o;
    }
}

// ---------------------------------------------------------------------------
extern "C" void kernel_launch(void* const* d_in, const int* in_sizes, int n_in,
                              void* d_out, int out_size) {
    const float* inputs     = (const float*)d_in[0];
    const float* qkv_w      = (const float*)d_in[1];
    const float* proj_w     = (const float*)d_in[2];
    const float* proj_b     = (const float*)d_in[3];
    const float* bias_table = (const float*)d_in[4];
    const float* g1         = (const float*)d_in[5];
    const float* b1         = (const float*)d_in[6];
    const float* g2         = (const float*)d_in[7];
    const float* b2         = (const float*)d_in[8];
    const float* w1         = (const float*)d_in[9];
    const float* bb1        = (const float*)d_in[10];
    const float* w2         = (const float*)d_in[11];
    const float* bb2        = (const float*)d_in[12];
    float* out = (float*)d_out;

    const int smemA = (4*64*AS)*2 + 36864 + 484*4 + 64*4 + 64*4;   // 108944 B
    const int smemB = (2*64*AS)*2 + 34816;                          // 69632 B

    cudaFuncSetAttribute(swin_attn_kernel, cudaFuncAttributeMaxDynamicSharedMemorySize, smemA);
    cudaFuncSetAttribute(swin_mlp_kernel,  cudaFuncAttributeMaxDynamicSharedMemorySize, smemB);

    cvt_weights_kernel<<<192, 256>>>(qkv_w, proj_w, w1, w2);
    swin_attn_kernel<<<4096, 256, smemA>>>(inputs, proj_b, bias_table, g1, b1, out);
    swin_mlp_kernel<<<4096, 256, smemB>>>(bb1, bb2, g2, b2, out);
}

// round 14
// speedup vs baseline: 1.0145x; 1.0145x over previous
#include <cuda_runtime.h>
#include <cuda_fp16.h>
#include <mma.h>
#include <math.h>
#include <stdint.h>
#include <cstdint>

using namespace nvcuda;

#define AS 136    // fp16 tile stride (halfs, mult of 8)
#define FS 136    // f32 scratch stride (floats)
#define HS2 136   // half scratch stride (halfs)
#define SHS 72    // fp16 score row stride (halfs, mult of 8)
#define HB (64*SHS)  // per-head S block (halfs)
#define RFS 132   // residual f32 row stride (floats, mult of 4)

// fp16 pre-converted weights (written by cvt_weights_kernel each launch)
// Q columns of qkv_w are pre-scaled by 1/sqrt(HD).
__device__ __align__(16) __half g_qkvwh[128*384];
__device__ __align__(16) __half g_projwh[128*128];
__device__ __align__(16) __half g_w1h[128*512];
__device__ __align__(16) __half g_w2h[512*128];

// ---------------------------------------------------------------------------
__global__ void cvt_weights_kernel(const float* __restrict__ qkv_w,
                                   const float* __restrict__ proj_w,
                                   const float* __restrict__ w1,
                                   const float* __restrict__ w2)
{
    const int i4 = (blockIdx.x*256 + threadIdx.x) * 4;   // grid 192 -> 196608
    const float* src; __half* dst; int off;
    float scale = 1.f;
    if (i4 < 49152) {
        src = qkv_w;  dst = g_qkvwh;  off = i4;
        if ((off % 384) < 128) scale = 0.17677669529663687f;   // fold qscale into Q
    }
    else if (i4 < 65536)  { src = proj_w; dst = g_projwh; off = i4 - 49152; }
    else if (i4 < 131072) { src = w1;     dst = g_w1h;    off = i4 - 65536; }
    else                  { src = w2;     dst = g_w2h;    off = i4 - 131072; }
    const float4 v = *(const float4*)(src + off);
    dst[off+0] = __float2half(v.x*scale); dst[off+1] = __float2half(v.y*scale);
    dst[off+2] = __float2half(v.z*scale); dst[off+3] = __float2half(v.w*scale);
}

// ---------------------------------------------------------------------------
// Fused kernel: LN1 -> QKV -> attention -> proj -> residual (smem) ->
//               LN2 -> MLP (4 chunks) -> final residual scatter.
// One CTA per window (64 rows), grid 4096, 256 threads, 2 CTA/SM.
// The window partition is a row bijection, so the MLP's row-local work is
// fully contained in the CTA that produced those attention-output rows.
// ---------------------------------------------------------------------------
__global__ void __launch_bounds__(256, 2) swin_block_kernel(
    const float* __restrict__ inp,
    const float* __restrict__ proj_b,
    const float* __restrict__ bias_table,
    const float* __restrict__ g1,
    const float* __restrict__ b1,
    const float* __restrict__ g2,
    const float* __restrict__ b2,
    const float* __restrict__ bb1,
    const float* __restrict__ bb2,
    float* __restrict__ out)
{
    extern __shared__ char sma[];
    __half* Xh = (__half*)sma;            // 64*AS (LN'd X; O; later MLP A1)
    __half* Qh = Xh + 64*AS;              // Q; later MLP A2
    __half* Kh = Qh + 64*AS;              // K; later Rf (f32 residual rows)
    __half* Vh = Kh + 64*AS;              // V; Rf tail
    char*   U  = (char*)(Vh + 64*AS);     // 36864B union: Wc / Sh / Ph2 / Hs / Ff
    __half* Wc  = (__half*)U;             // 128*AS halfs (34816B)
    __half* Sh  = (__half*)U;             // 4*HB halfs (36864B)
    __half* Ph2 = (__half*)U;             // 64*HS2 halfs proj scratch
    __half* Hs  = (__half*)U;             // 64*HS2 halfs gemm1 scratch
    float*  Ff  = (float*)U;              // 64*FS floats gemm2 scratch
    float*  Rf  = (float*)Kh;             // 64*RFS floats residual (33792B <= 34816B)
    float*  bias_s = (float*)(U + 36864); // 484
    int*    lab_s  = (int*)(bias_s + 484);
    int*    orow_s = lab_s + 64;

    const int tid = threadIdx.x;
    const int warp = tid >> 5, lane = tid & 31;
    const int wblk = blockIdx.x;
    const int bb = wblk >> 9;
    const int wi = wblk & 511;
    const int gx = wi >> 6, gy = (wi >> 3) & 7, gz = wi & 7;

    for (int i = tid; i < 484; i += 256) bias_s[i] = bias_table[i];

    if (tid < 64) {
        const int lx = tid >> 4, ly = (tid >> 2) & 3, lz = tid & 3;
        const int px = gx*4 + lx, py = gy*4 + ly, pz = gz*4 + lz;
        const int ox = (px + 2) & 31, oy = (py + 2) & 31, oz = (pz + 2) & 31;
        orow_s[tid] = ((bb*32 + ox)*32 + oy)*32 + oz;
        const int labx = px < 28 ? 0 : (px < 30 ? 1 : 2);
        const int laby = py < 28 ? 0 : (py < 30 ? 1 : 2);
        const int labz = pz < 28 ? 0 : (pz < 30 ? 1 : 2);
        lab_s[tid] = labx*9 + laby*3 + labz;
    }
    __syncthreads();

    // ---- Phase 1: LayerNorm -> fp16 Xh ----
    {
        const float4 gv = *(const float4*)(g1 + lane*4);
        const float4 bv = *(const float4*)(b1 + lane*4);
        for (int t = warp*8; t < warp*8 + 8; ++t) {
            const float* row = inp + (long)orow_s[t]*128;
            const float4 x4 = *(const float4*)(row + lane*4);
            float s = x4.x + x4.y + x4.z + x4.w;
            float q = x4.x*x4.x + x4.y*x4.y + x4.z*x4.z + x4.w*x4.w;
            #pragma unroll
            for (int o = 16; o; o >>= 1) {
                s += __shfl_xor_sync(0xffffffffu, s, o);
                q += __shfl_xor_sync(0xffffffffu, q, o);
            }
            const float m = s * 0.0078125f;
            const float rstd = rsqrtf(q*0.0078125f - m*m + 1e-5f);
            __half* dst = Xh + t*AS + lane*4;
            dst[0] = __float2half((x4.x - m)*rstd*gv.x + bv.x);
            dst[1] = __float2half((x4.y - m)*rstd*gv.y + bv.y);
            dst[2] = __float2half((x4.z - m)*rstd*gv.z + bv.z);
            dst[3] = __float2half((x4.w - m)*rstd*gv.w + bv.w);
        }
    }

    const int rt2 = warp >> 2;            // 32-row half (0..1)
    const int ct2 = warp & 3;             // 32-col quarter (0..3)

    // ---- Phase 2: QKV via wmma, half accumulators, direct fp16 stores ----
    for (int c = 0; c < 3; ++c) {
        __syncthreads();
        for (int idx = tid; idx < 2048; idx += 256) {
            const int k = idx >> 4, u = idx & 15;
            *(uint4*)(Wc + k*AS + u*8) = *(const uint4*)(g_qkvwh + k*384 + c*128 + u*8);
        }
        __syncthreads();
        wmma::fragment<wmma::accumulator, 16, 16, 16, __half> c1[2][2];
        #pragma unroll
        for (int i = 0; i < 2; ++i)
            #pragma unroll
            for (int j = 0; j < 2; ++j) wmma::fill_fragment(c1[i][j], __float2half(0.f));
        #pragma unroll
        for (int ks = 0; ks < 8; ++ks) {
            wmma::fragment<wmma::matrix_a, 16, 16, 16, __half, wmma::row_major> fa[2];
            wmma::fragment<wmma::matrix_b, 16, 16, 16, __half, wmma::row_major> fb[2];
            #pragma unroll
            for (int i = 0; i < 2; ++i)
                wmma::load_matrix_sync(fa[i], Xh + (rt2*32 + i*16)*AS + ks*16, AS);
            #pragma unroll
            for (int j = 0; j < 2; ++j)
                wmma::load_matrix_sync(fb[j], Wc + ks*16*AS + ct2*32 + j*16, AS);
            #pragma unroll
            for (int i = 0; i < 2; ++i)
                #pragma unroll
                for (int j = 0; j < 2; ++j) wmma::mma_sync(c1[i][j], fa[i], fb[j], c1[i][j]);
        }
        __half* dest = (c == 0) ? Qh : (c == 1) ? Kh : Vh;
        #pragma unroll
        for (int i = 0; i < 2; ++i)
            #pragma unroll
            for (int j = 0; j < 2; ++j)
                wmma::store_matrix_sync(dest + (rt2*32 + i*16)*AS + ct2*32 + j*16, c1[i][j], AS, wmma::mem_row_major);
    }
    __syncthreads();        // Q/K/V visible; Wc reads done -> U reusable as Sh

    // ---- Phase 3: all-heads attention ----
    {
        const int h = warp >> 1;
        const int p = warp & 1;
        wmma::fragment<wmma::accumulator, 16, 16, 16, __half> sc[2][4];
        #pragma unroll
        for (int i = 0; i < 2; ++i)
            #pragma unroll
            for (int j = 0; j < 4; ++j) wmma::fill_fragment(sc[i][j], __float2half(0.f));
        #pragma unroll
        for (int ks = 0; ks < 2; ++ks) {
            wmma::fragment<wmma::matrix_a, 16, 16, 16, __half, wmma::row_major> fa[2];
            wmma::fragment<wmma::matrix_b, 16, 16, 16, __half, wmma::col_major> fb[4];
            #pragma unroll
            for (int i = 0; i < 2; ++i)
                wmma::load_matrix_sync(fa[i], Qh + (p*32 + i*16)*AS + h*32 + ks*16, AS);
            #pragma unroll
            for (int j = 0; j < 4; ++j)
                wmma::load_matrix_sync(fb[j], Kh + j*16*AS + h*32 + ks*16, AS);
            #pragma unroll
            for (int i = 0; i < 2; ++i)
                #pragma unroll
                for (int j = 0; j < 4; ++j) wmma::mma_sync(sc[i][j], fa[i], fb[j], sc[i][j]);
        }
        #pragma unroll
        for (int i = 0; i < 2; ++i)
            #pragma unroll
            for (int j = 0; j < 4; ++j)
                wmma::store_matrix_sync(Sh + h*HB + (p*32 + i*16)*SHS + j*16, sc[i][j], SHS, wmma::mem_row_major);
    }
    __syncthreads();

    // softmax: one thread per (head, row), fully in registers (half2)
    {
        const int shh = tid >> 6;
        const int si  = tid & 63;
        __half* Srow = Sh + shh*HB + si*SHS;
        const int li = lab_s[si];
        const int lxi = si >> 4, lyi = (si >> 2) & 3, lzi = si & 3;
        half2 av[32];
        float mx = -1e30f;
        #pragma unroll
        for (int t = 0; t < 32; ++t) {
            const int j0 = 2*t;
            const float2 s2 = __half22float2(*(half2*)(Srow + j0));
            const int lxj = j0 >> 4, lyj = (j0 >> 2) & 3, lzj = j0 & 3;
            const int brow = 11*(lxi - lxj + 3) + (lyi - lyj + 3) + (lzi - lzj + 3);
            float a0 = s2.x + bias_s[brow*4 + shh];
            float a1 = s2.y + bias_s[(brow-1)*4 + shh];
            if (lab_s[j0]   != li) a0 -= 100.f;
            if (lab_s[j0+1] != li) a1 -= 100.f;
            mx = fmaxf(mx, fmaxf(a0, a1));
            av[t] = __floats2half2_rn(a0, a1);
        }
        const half2 mx2 = __float2half2_rn(mx);
        float sum = 0.f;
        #pragma unroll
        for (int t = 0; t < 32; ++t) {
            av[t] = h2exp(__hsub2(av[t], mx2));
            const float2 e2 = __half22float2(av[t]);
            sum += e2.x + e2.y;
        }
        const half2 inv2 = __float2half2_rn(1.f / sum);
        #pragma unroll
        for (int t = 0; t < 32; ++t)
            *(half2*)(Srow + 2*t) = __hmul2(av[t], inv2);
    }
    __syncthreads();

    // PV (all heads): half acc, store direct into Xh (O)
    {
        const int hh = warp & 3;
        const int rp = warp >> 2;
        wmma::fragment<wmma::accumulator, 16, 16, 16, __half> oc[2][2];
        #pragma unroll
        for (int i = 0; i < 2; ++i)
            #pragma unroll
            for (int j = 0; j < 2; ++j) wmma::fill_fragment(oc[i][j], __float2half(0.f));
        #pragma unroll
        for (int ks = 0; ks < 4; ++ks) {
            wmma::fragment<wmma::matrix_a, 16, 16, 16, __half, wmma::row_major> fa[2];
            wmma::fragment<wmma::matrix_b, 16, 16, 16, __half, wmma::row_major> fb[2];
            #pragma unroll
            for (int i = 0; i < 2; ++i)
                wmma::load_matrix_sync(fa[i], Sh + hh*HB + (rp*32 + i*16)*SHS + ks*16, SHS);
            #pragma unroll
            for (int j = 0; j < 2; ++j)
                wmma::load_matrix_sync(fb[j], Vh + ks*16*AS + hh*32 + j*16, AS);
            #pragma unroll
            for (int i = 0; i < 2; ++i)
                #pragma unroll
                for (int j = 0; j < 2; ++j) wmma::mma_sync(oc[i][j], fa[i], fb[j], oc[i][j]);
        }
        #pragma unroll
        for (int i = 0; i < 2; ++i)
            #pragma unroll
            for (int j = 0; j < 2; ++j)
                wmma::store_matrix_sync(Xh + (rp*32 + i*16)*AS + hh*32 + j*16, oc[i][j], AS, wmma::mem_row_major);
    }
    __syncthreads();        // Sh reads done -> U reusable as Wc; Xh (O) visible

    // ---- Phase 4: proj via wmma (half acc) -> Ph2 ----
    for (int idx = tid; idx < 2048; idx += 256) {
        const int k = idx >> 4, u = idx & 15;
        *(uint4*)(Wc + k*AS + u*8) = *(const uint4*)(g_projwh + k*128 + u*8);
    }
    __syncthreads();
    {
        wmma::fragment<wmma::accumulator, 16, 16, 16, __half> pc[2][2];
        #pragma unroll
        for (int i = 0; i < 2; ++i)
            #pragma unroll
            for (int j = 0; j < 2; ++j) wmma::fill_fragment(pc[i][j], __float2half(0.f));
        #pragma unroll
        for (int ks = 0; ks < 8; ++ks) {
            wmma::fragment<wmma::matrix_a, 16, 16, 16, __half, wmma::row_major> fa[2];
            wmma::fragment<wmma::matrix_b, 16, 16, 16, __half, wmma::row_major> fb[2];
            #pragma unroll
            for (int i = 0; i < 2; ++i)
                wmma::load_matrix_sync(fa[i], Xh + (rt2*32 + i*16)*AS + ks*16, AS);
            #pragma unroll
            for (int j = 0; j < 2; ++j)
                wmma::load_matrix_sync(fb[j], Wc + ks*16*AS + ct2*32 + j*16, AS);
            #pragma unroll
            for (int i = 0; i < 2; ++i)
                #pragma unroll
                for (int j = 0; j < 2; ++j) wmma::mma_sync(pc[i][j], fa[i], fb[j], pc[i][j]);
        }
        __syncthreads();    // Wc reads + Xh reads done -> U as Ph2; Xh reusable
        #pragma unroll
        for (int i = 0; i < 2; ++i)
            #pragma unroll
            for (int j = 0; j < 2; ++j)
                wmma::store_matrix_sync(Ph2 + (rt2*32 + i*16)*HS2 + ct2*32 + j*16, pc[i][j], HS2, wmma::mem_row_major);
    }
    __syncthreads();

    // ---- Phase 5: residual rows -> smem Rf (f32), no global write ----
    // (K/V tiles are dead; Rf overlays them.)
    for (int idx = tid; idx < 2048; idx += 256) {
        const int r = idx >> 5, cg = idx & 31;
        const long base = (long)orow_s[r]*128;
        const half2 v01 = *(half2*)(Ph2 + r*HS2 + cg*4);
        const half2 v23 = *(half2*)(Ph2 + r*HS2 + cg*4 + 2);
        const float2 f01 = __half22float2(v01);
        const float2 f23 = __half22float2(v23);
        const float4 pb = *(const float4*)(proj_b + cg*4);
        const float4 xin = *(const float4*)(inp + base + cg*4);
        float4 o;
        o.x = 0.5f*(f01.x + pb.x) + xin.x;
        o.y = 0.5f*(f01.y + pb.y) + xin.y;
        o.z = 0.5f*(f23.x + pb.z) + xin.z;
        o.w = 0.5f*(f23.y + pb.w) + xin.w;
        *(float4*)(Rf + r*RFS + cg*4) = o;
    }
    __syncthreads();        // Rf visible; Ph2 reads done -> U free

    // ---- Phase 6: LN2 on Rf -> fp16 A1 (over Xh) ----
    {
        const float4 gv = *(const float4*)(g2 + lane*4);
        const float4 bv = *(const float4*)(b2 + lane*4);
        for (int t = warp*8; t < warp*8 + 8; ++t) {
            const float4 x4 = *(const float4*)(Rf + t*RFS + lane*4);
            float s = x4.x + x4.y + x4.z + x4.w;
            float q = x4.x*x4.x + x4.y*x4.y + x4.z*x4.z + x4.w*x4.w;
            #pragma unroll
            for (int o = 16; o; o >>= 1) {
                s += __shfl_xor_sync(0xffffffffu, s, o);
                q += __shfl_xor_sync(0xffffffffu, q, o);
            }
            const float m = s * 0.0078125f;
            const float rstd = rsqrtf(q*0.0078125f - m*m + 1e-5f);
            __half* dst = Xh + t*AS + lane*4;
            dst[0] = __float2half((x4.x - m)*rstd*gv.x + bv.x);
            dst[1] = __float2half((x4.y - m)*rstd*gv.y + bv.y);
            dst[2] = __float2half((x4.z - m)*rstd*gv.z + bv.z);
            dst[3] = __float2half((x4.w - m)*rstd*gv.w + bv.w);
        }
    }

    // ---- Phase 7: MLP, 4 chunks; A1=Xh, A2=Qh, scratch in U ----
    wmma::fragment<wmma::accumulator, 16, 16, 16, float> acc2[2][2];
    #pragma unroll
    for (int i = 0; i < 2; ++i)
        #pragma unroll
        for (int j = 0; j < 2; ++j) wmma::fill_fragment(acc2[i][j], 0.f);

    for (int nb = 0; nb < 4; ++nb) {
        __syncthreads();    // A1 visible (nb=0) / prev gemm2 Wc reads done
        for (int idx = tid; idx < 2048; idx += 256) {
            const int k = idx >> 4, u = idx & 15;
            *(uint4*)(Wc + k*AS + u*8) = *(const uint4*)(g_w1h + k*512 + nb*128 + u*8);
        }
        __syncthreads();

        wmma::fragment<wmma::accumulator, 16, 16, 16, __half> c1[2][2];
        #pragma unroll
        for (int i = 0; i < 2; ++i)
            #pragma unroll
            for (int j = 0; j < 2; ++j) wmma::fill_fragment(c1[i][j], __float2half(0.f));
        #pragma unroll
        for (int ks = 0; ks < 8; ++ks) {
            wmma::fragment<wmma::matrix_a, 16, 16, 16, __half, wmma::row_major> fa[2];
            wmma::fragment<wmma::matrix_b, 16, 16, 16, __half, wmma::row_major> fb[2];
            #pragma unroll
            for (int i = 0; i < 2; ++i)
                wmma::load_matrix_sync(fa[i], Xh + (rt2*32 + i*16)*AS + ks*16, AS);
            #pragma unroll
            for (int j = 0; j < 2; ++j)
                wmma::load_matrix_sync(fb[j], Wc + ks*16*AS + ct2*32 + j*16, AS);
            #pragma unroll
            for (int i = 0; i < 2; ++i)
                #pragma unroll
                for (int j = 0; j < 2; ++j) wmma::mma_sync(c1[i][j], fa[i], fb[j], c1[i][j]);
        }
        __syncthreads();    // Wc reads done -> overlay Hs
        #pragma unroll
        for (int i = 0; i < 2; ++i)
            #pragma unroll
            for (int j = 0; j < 2; ++j)
                wmma::store_matrix_sync(Hs + (rt2*32 + i*16)*HS2 + ct2*32 + j*16, c1[i][j], HS2, wmma::mem_row_major);
        __syncthreads();

        // bias + exact GELU -> fp16 A2 (over Qh)
        for (int idx = tid; idx < 2048; idx += 256) {
            const int r = idx >> 5, cg = idx & 31;
            const half2 v01 = *(half2*)(Hs + r*HS2 + cg*4);
            const half2 v23 = *(half2*)(Hs + r*HS2 + cg*4 + 2);
            const float2 f01 = __half22float2(v01);
            const float2 f23 = __half22float2(v23);
            const float4 bv = *(const float4*)(bb1 + nb*128 + cg*4);
            float h0 = f01.x + bv.x, h1 = f01.y + bv.y, h2 = f23.x + bv.z, h3 = f23.y + bv.w;
            h0 = h0 * 0.5f * (1.f + erff(h0 * 0.70710678118654752f));
            h1 = h1 * 0.5f * (1.f + erff(h1 * 0.70710678118654752f));
            h2 = h2 * 0.5f * (1.f + erff(h2 * 0.70710678118654752f));
            h3 = h3 * 0.5f * (1.f + erff(h3 * 0.70710678118654752f));
            __half* dst = Qh + r*AS + cg*4;
            dst[0] = __float2half(h0); dst[1] = __float2half(h1);
            dst[2] = __float2half(h2); dst[3] = __float2half(h3);
        }
        __syncthreads();    // Hs reads done -> overlay Wc (w2 chunk)
        for (int idx = tid; idx < 2048; idx += 256) {
            const int k = idx >> 4, u = idx & 15;
            *(uint4*)(Wc + k*AS + u*8) = *(const uint4*)(g_w2h + (nb*128 + k)*128 + u*8);
        }
        __syncthreads();

        #pragma unroll
        for (int ks = 0; ks < 8; ++ks) {
            wmma::fragment<wmma::matrix_a, 16, 16, 16, __half, wmma::row_major> fa[2];
            wmma::fragment<wmma::matrix_b, 16, 16, 16, __half, wmma::row_major> fb[2];
            #pragma unroll
            for (int i = 0; i < 2; ++i)
                wmma::load_matrix_sync(fa[i], Qh + (rt2*32 + i*16)*AS + ks*16, AS);
            #pragma unroll
            for (int j = 0; j < 2; ++j)
                wmma::load_matrix_sync(fb[j], Wc + ks*16*AS + ct2*32 + j*16, AS);
            #pragma unroll
            for (int i = 0; i < 2; ++i)
                #pragma unroll
                for (int j = 0; j < 2; ++j) wmma::mma_sync(acc2[i][j], fa[i], fb[j], acc2[i][j]);
        }
    }

    __syncthreads();        // Wc reads done -> overlay Ff
    #pragma unroll
    for (int i = 0; i < 2; ++i)
        #pragma unroll
        for (int j = 0; j < 2; ++j)
            wmma::store_matrix_sync(Ff + (rt2*32 + i*16)*FS + ct2*32 + j*16, acc2[i][j], FS, wmma::mem_row_major);
    __syncthreads();

    // ---- Phase 8: final residual scatter to global ----
    for (int idx = tid; idx < 2048; idx += 256) {
        const int r = idx >> 5, cg = idx & 31;
        const long base = (long)orow_s[r]*128;
        const float4 v  = *(const float4*)(Ff + r*FS + cg*4);
        const float4 bv = *(const float4*)(bb2 + cg*4);
        const float4 rv = *(const float4*)(Rf + r*RFS + cg*4);
        float4 o;
        o.x = 0.5f*(v.x + bv.x) + rv.x;
        o.y = 0.5f*(v.y + bv.y) + rv.y;
        o.z = 0.5f*(v.z + bv.z) + rv.z;
        o.w = 0.5f*(v.w + bv.w) + rv.w;
        *(float4*)(out + base + cg*4) = o;
    }
}

// ---------------------------------------------------------------------------
extern "C" void kernel_launch(void* const* d_in, const int* in_sizes, int n_in,
                              void* d_out, int out_size) {
    const float* inputs     = (const float*)d_in[0];
    const float* qkv_w      = (const float*)d_in[1];
    const float* proj_w     = (const float*)d_in[2];
    const float* proj_b     = (const float*)d_in[3];
    const float* bias_table = (const float*)d_in[4];
    const float* g1         = (const float*)d_in[5];
    const float* b1         = (const float*)d_in[6];
    const float* g2         = (const float*)d_in[7];
    const float* b2         = (const float*)d_in[8];
    const float* w1         = (const float*)d_in[9];
    const float* bb1        = (const float*)d_in[10];
    const float* w2         = (const float*)d_in[11];
    const float* bb2        = (const float*)d_in[12];
    float* out = (float*)d_out;

    const int smemA = (4*64*AS)*2 + 36864 + 484*4 + 64*4 + 64*4;   // 108944 B

    cudaFuncSetAttribute(swin_block_kernel, cudaFuncAttributeMaxDynamicSharedMemorySize, smemA);

    cvt_weights_kernel<<<192, 256>>>(qkv_w, proj_w, w1, w2);
    swin_block_kernel<<<4096, 256, smemA>>>(inputs, proj_b, bias_table,
                                            g1, b1, g2, b2, bb1, bb2, out);
}